// round 9
// baseline (speedup 1.0000x reference)
#include <cuda_runtime.h>
#include <math.h>

#define PH 7
#define PW 7
#define C  256
#define MAXN 1024

// Scratch (device globals; no allocation allowed)
__device__ float4 g_scoord[MAXN];  // per-sorted-roi (ybase, ystep, xbase, xstep) in feature coords
__device__ int    g_slvl[MAXN];    // sorted levels

// ---------------------------------------------------------------------------
// Kernel 1: per-roi level + coordinate bases, stable counting sort.
// Packed 4x16-bit counters in uint64; warp-shuffle inclusive scan + warp-total
// combine. Single block, 1024 threads, N <= 1024.
// ---------------------------------------------------------------------------
__global__ void level_sort_kernel(const float* __restrict__ rois, int N) {
    __shared__ unsigned long long warp_tot[32];
    int i    = threadIdx.x;
    int lane = i & 31;
    int wid  = i >> 5;

    int lvl = 0;
    float4 cb = make_float4(0.f, 0.f, 0.f, 0.f);
    unsigned long long v = 0ULL;

    if (i < N) {
        float y1 = rois[i * 4 + 0];
        float x1 = rois[i * 4 + 1];
        float y2 = rois[i * 4 + 2];
        float x2 = rois[i * 4 + 3];
        float h = y2 - y1;
        float w = x2 - x1;
        // match reference fp32 path: log(sqrt(h*w))/log(2) - 5, round-half-even
        float lf = logf(sqrtf(h * w)) * (1.0f / logf(2.0f)) - 5.0f;
        int l = (int)rintf(lf);
        l = min(max(l, 0), 3);
        lvl = l;
        const float inv = 1.0f / 1024.0f;
        float ny1 = y1 * inv, nx1 = x1 * inv, ny2 = y2 * inv, nx2 = x2 * inv;
        float Hm1 = (float)((256 >> l) - 1);
        float Wm1 = Hm1;
        cb.x = ny1 * Hm1;                              // ybase
        cb.y = (ny2 - ny1) * Hm1 * (1.0f / (PH - 1));  // ystep
        cb.z = nx1 * Wm1;                              // xbase
        cb.w = (nx2 - nx1) * Wm1 * (1.0f / (PW - 1));  // xstep
        v = 1ULL << (16 * lvl);
    }

    // warp inclusive scan (64-bit)
    unsigned long long incl = v;
#pragma unroll
    for (int off = 1; off < 32; off <<= 1) {
        unsigned long long t = __shfl_up_sync(0xFFFFFFFFu, incl, off);
        if (lane >= off) incl += t;
    }
    if (lane == 31) warp_tot[wid] = incl;
    __syncthreads();

    if (wid == 0) {
        unsigned long long wt = warp_tot[lane];
#pragma unroll
        for (int off = 1; off < 32; off <<= 1) {
            unsigned long long t = __shfl_up_sync(0xFFFFFFFFu, wt, off);
            if (lane >= off) wt += t;
        }
        warp_tot[lane] = wt;
    }
    __syncthreads();

    unsigned long long total = warp_tot[31];
    unsigned long long offset = (wid > 0) ? warp_tot[wid - 1] : 0ULL;
    incl += offset;

    if (i < N) {
        int rank = (int)((incl >> (16 * lvl)) & 0xFFFFULL) - 1;
        int base = 0;
#pragma unroll
        for (int l = 0; l < 4; l++)
            if (l < lvl) base += (int)((total >> (16 * l)) & 0xFFFFULL);
        int pos = base + rank;
        g_slvl[pos] = lvl;
        g_scoord[pos] = cb;
    }
}

// ---------------------------------------------------------------------------
// Kernel 2: bilinear gather with SCALAR loads.
// grid = (N, PH); block = 256 (thread = one channel).
// Every warp LDG.32 is one fully-coalesced 128B line = ONE L1 wavefront,
// served at the 1.0 cyc/wf cross-LDG rate — vs LDG.128's 4 within-instruction
// wavefronts at ~2.07 cyc/wf replay rate, which capped all float4 variants at
// L1~50%. Full px unroll keeps 28 one-register loads in flight per thread.
// Weight-form bilinear: 4 FMA/channel, depth-1 tree.
// ---------------------------------------------------------------------------
__global__ void __launch_bounds__(256, 3)
roi_align_kernel(const float* __restrict__ f0,
                 const float* __restrict__ f1,
                 const float* __restrict__ f2,
                 const float* __restrict__ f3,
                 float* __restrict__ out) {
    int roi = blockIdx.x;
    int py  = blockIdx.y;
    int c   = threadIdx.x;   // 0..255 channel

    float4 cb = g_scoord[roi];
    int lvl = g_slvl[roi];

    const float* f = (lvl == 0) ? f0 : (lvl == 1) ? f1 : (lvl == 2) ? f2 : f3;
    int W = 256 >> lvl;
    float Wm1 = (float)(W - 1);

    float iy = cb.x + (float)py * cb.y;
    float y0f = floorf(iy);
    float ly = iy - y0f;
    int y0 = min(max((int)y0f, 0), W - 1);
    int y1 = min(max((int)y0f + 1, 0), W - 1);
    bool vy = (iy >= 0.0f) && (iy <= Wm1);
    float omly = 1.0f - ly;

    const float* row0 = f + (size_t)y0 * W * C + c;
    const float* row1 = f + (size_t)y1 * W * C + c;
    float* o = out + ((size_t)(roi * PH + py) * PW) * C + c;

#pragma unroll
    for (int px = 0; px < PW; px++) {
        float ix = cb.z + (float)px * cb.w;
        float x0f = floorf(ix);
        float lx = ix - x0f;
        int x0 = min(max((int)x0f, 0), W - 1);
        int x1 = min(max((int)x0f + 1, 0), W - 1);
        bool vx = (ix >= 0.0f) && (ix <= Wm1);

        float f00 = __ldg(row0 + x0 * C);
        float f01 = __ldg(row0 + x1 * C);
        float f10 = __ldg(row1 + x0 * C);
        float f11 = __ldg(row1 + x1 * C);

        float omlx = 1.0f - lx;
        float w00 = omlx * omly;
        float w01 = lx * omly;
        float w10 = omlx * ly;
        float w11 = lx * ly;

        float r = fmaf(f11, w11, fmaf(f10, w10, fmaf(f01, w01, f00 * w00)));
        if (!(vy && vx)) r = 0.0f;
        __stcs(o + px * C, r);
    }
}

extern "C" void kernel_launch(void* const* d_in, const int* in_sizes, int n_in,
                              void* d_out, int out_size) {
    const float* f0   = (const float*)d_in[0];
    const float* f1   = (const float*)d_in[1];
    const float* f2   = (const float*)d_in[2];
    const float* f3   = (const float*)d_in[3];
    const float* rois = (const float*)d_in[4];
    float* out = (float*)d_out;

    int N = in_sizes[4] / 4;
    if (N > MAXN) N = MAXN;

    level_sort_kernel<<<1, 1024>>>(rois, N);

    dim3 grid(N, PH);
    roi_align_kernel<<<grid, 256>>>(f0, f1, f2, f3, out);
}